// round 8
// baseline (speedup 1.0000x reference)
#include <cuda_runtime.h>
#include <cuda_pipeline.h>

typedef unsigned long long ull;

// Problem dims
#define NC_  31
#define NXL  256
#define NYL  256
#define NO_  3
#define KXL  17
#define KYL  17
#define NG_  (NO_ * NC_)   // 93
#define WIN_ 9

// Compact weights: per (o,c) group a 9x9 tile of broadcast (v,v) float2 pairs
__device__ float2 g_w2[NG_ * 81];
__device__ int    g_ori[NG_];     // (kx0 << 8) | ky0
__device__ unsigned g_tilectr;    // persistent-kernel work queue

// ---------------------------------------------------------------------------
// Fused prep: one warp per group (origin via shfl-min, then scatter).
// Also resets the tile queue counter for the conv kernel.
// ---------------------------------------------------------------------------
__global__ void prep_all(const float* __restrict__ vk,
                         const int* __restrict__ loc) {
    if (blockIdx.x == 0 && threadIdx.x == 0) g_tilectr = 0u;

    int w    = (blockIdx.x * blockDim.x + threadIdx.x) >> 5;
    int lane = threadIdx.x & 31;
    if (w >= NG_) return;

    int kxm = 1 << 30, kym = 1 << 30;
    int idxs[3]; float vs[3];
#pragma unroll
    for (int s = 0; s < 3; ++s) {
        int t = lane + 32 * s;
        if (t < 81) {
            int idx = loc[w * 81 + t];
            idxs[s] = idx;
            vs[s]   = vk[w * 81 + t];
            int ky = idx % KYL;
            int kx = (idx / KYL) % KXL;
            kxm = min(kxm, kx);
            kym = min(kym, ky);
        }
    }
#pragma unroll
    for (int off = 16; off; off >>= 1) {
        kxm = min(kxm, __shfl_xor_sync(0xffffffffu, kxm, off));
        kym = min(kym, __shfl_xor_sync(0xffffffffu, kym, off));
    }
    if (lane == 0) g_ori[w] = (kxm << 8) | kym;

#pragma unroll
    for (int s = 0; s < 3; ++s) {
        int t = lane + 32 * s;
        if (t < 81) {
            int idx = idxs[s];
            float v = fmaxf(vs[s], 0.0f);
            int ky = idx % KYL;
            int kx = (idx / KYL) % KXL;
            g_w2[w * 81 + (kx - kxm) * WIN_ + (ky - kym)] = make_float2(v, v);
        }
    }
}

// ---------------------------------------------------------------------------
// Persistent conv. 444 blocks (3/SM x 148) claim 32x128 tiles from an atomic
// queue. Cross-tile double-buffer: while computing the last channel of tile T,
// channel 0 of tile T+1 is staged into the other buffer (tile id prefetched
// two channels earlier behind existing barriers). Math core unchanged:
// 8B cp.async staging, XOR-swizzled LDS.128 operands, dual-phase fma.rn.f32x2.
// ---------------------------------------------------------------------------
#define TH 32
#define TW 128
#define NTILES 768             // 16 b * 3 o * 8 ir * 2 jc
#define NBLOCKS 444            // 148 SMs * 3 resident blocks
#define SRO 40                 // staged rows (TH + 8)
#define SWF 160                // smem row stride in floats
#define ROWB (SWF * 4)         // 640 bytes
#define TILE_B (SRO * ROWB)    // 25600 bytes
#define WPAD 10                // weight row stride in ull
#define WBUF (WIN_ * WPAD)     // 90 ull
#define SMEM_BYTES (2 * TILE_B + 2 * WBUF * 8 + NG_ * 4 + 16)

#define FMA2(acc, a, b) \
    asm("fma.rn.f32x2 %0, %1, %2, %0;" : "+l"(acc) : "l"(a), "l"(b))

__device__ __forceinline__ int swz_unit(int cu) {
    return cu ^ ((cu >> 3) & 7);
}

__device__ __forceinline__ void ldE(const char* p, ull& a, ull& b) {
    longlong2 L = *(const longlong2*)p;
    a = (ull)L.x; b = (ull)L.y;
}

// Channel math, parity variant SV = ky0 & 1 (see prior rounds).
template<int SV>
__device__ __forceinline__ void channel_math(
        const char* __restrict__ tb, const char* __restrict__ wb,
        const int* offs, ull* accA, ull* accB) {
    ull P[14];
#pragma unroll
    for (int e = 0; e < 5; ++e)
        ldE(tb + offs[e], P[2 * e], P[2 * e + 1]);

#pragma unroll
    for (int u = 0; u < 9; ++u) {
        const int ro = u * ROWB;
        const int rn = ro + ROWB;
        const char* wr = wb + u * (WPAD * 8);
        ull N[10];
        ldE(tb + offs[5] + ro, P[10], P[11]);
        if (SV == 1)
            ldE(tb + offs[6] + ro, P[12], P[13]);

        ull w0, w1, w2, w3;
        ldE(wr, w0, w1);
        ldE(wr + 16, w2, w3);

        if (SV == 0) {
#pragma unroll
            for (int j = 0; j < 8; ++j) FMA2(accA[j], P[j], w0);
#pragma unroll
            for (int i = 0; i < 9; ++i) FMA2(accB[i], P[i], w1);
#pragma unroll
            for (int j = 0; j < 8; ++j) FMA2(accA[j], P[1 + j], w2);
#pragma unroll
            for (int i = 0; i < 9; ++i) FMA2(accB[i], P[1 + i], w3);
            if (u < 8) ldE(tb + offs[0] + rn, N[0], N[1]);
            ldE(wr + 32, w0, w1);
            ldE(wr + 48, w2, w3);
#pragma unroll
            for (int j = 0; j < 8; ++j) FMA2(accA[j], P[2 + j], w0);
#pragma unroll
            for (int i = 0; i < 9; ++i) FMA2(accB[i], P[2 + i], w1);
#pragma unroll
            for (int j = 0; j < 8; ++j) FMA2(accA[j], P[3 + j], w2);
#pragma unroll
            for (int i = 0; i < 9; ++i) FMA2(accB[i], P[3 + i], w3);
            if (u < 8) ldE(tb + offs[1] + rn, N[2], N[3]);
            const ull w8 = *(const ull*)(wr + 64);
#pragma unroll
            for (int j = 0; j < 8; ++j) FMA2(accA[j], P[4 + j], w8);
        } else {
#pragma unroll
            for (int i = 0; i < 9; ++i) FMA2(accB[i], P[i], w0);
#pragma unroll
            for (int j = 0; j < 8; ++j) FMA2(accA[j], P[1 + j], w1);
#pragma unroll
            for (int i = 0; i < 9; ++i) FMA2(accB[i], P[1 + i], w2);
#pragma unroll
            for (int j = 0; j < 8; ++j) FMA2(accA[j], P[2 + j], w3);
            if (u < 8) ldE(tb + offs[0] + rn, N[0], N[1]);
            ldE(wr + 32, w0, w1);
            ldE(wr + 48, w2, w3);
#pragma unroll
            for (int i = 0; i < 9; ++i) FMA2(accB[i], P[2 + i], w0);
#pragma unroll
            for (int j = 0; j < 8; ++j) FMA2(accA[j], P[3 + j], w1);
#pragma unroll
            for (int i = 0; i < 9; ++i) FMA2(accB[i], P[3 + i], w2);
#pragma unroll
            for (int j = 0; j < 8; ++j) FMA2(accA[j], P[4 + j], w3);
            if (u < 8) ldE(tb + offs[1] + rn, N[2], N[3]);
            const ull w8 = *(const ull*)(wr + 64);
#pragma unroll
            for (int i = 0; i < 9; ++i) FMA2(accB[i], P[4 + i], w8);
        }

        if (u < 8) {
            ldE(tb + offs[2] + rn, N[4], N[5]);
            ldE(tb + offs[3] + rn, N[6], N[7]);
            ldE(tb + offs[4] + rn, N[8], N[9]);
#pragma unroll
            for (int k = 0; k < 10; ++k) P[k] = N[k];
        }
    }
}

__global__ void __launch_bounds__(256, 3) conv_kernel(
        const float* __restrict__ x, float* __restrict__ out) {
    extern __shared__ float smem[];
    char* bufs[2] = { (char*)smem, (char*)smem + TILE_B };
    char* wbs[2];
    wbs[0] = bufs[1] + TILE_B;
    wbs[1] = wbs[0] + WBUF * 8;
    int*  s_ori = (int*)(wbs[1] + WBUF * 8);
    volatile int* s_t = (volatile int*)(s_ori + NG_);

    const int tid = threadIdx.x;
    const int tx  = tid & 7;
    const int ty  = tid >> 3;

    for (int i = tid; i < NG_; i += 256) s_ori[i] = g_ori[i];
    if (tid == 0) s_t[0] = (int)atomicAdd(&g_tilectr, 1u);
    __syncthreads();

    const int wdoff = ((tid / WIN_) * WPAD + tid % WIN_) * 8;
    const int half8 = (tx & 1) * 8;
    const int thcu  = tx >> 1;

    // tile id -> (b, o, i0, j0); t = ((b*3 + o)*8 + ir)*2 + jc
    // stage channel c of tile t into (tbuf, wbuf)
    auto stage = [&](int t, int c, char* tbuf, char* wbuf) {
        const int jc = t & 1, ir = (t >> 1) & 7, r3 = t >> 4;
        const int b = r3 / 3, o = r3 - 3 * b;
        const int i0 = ir * TH, j0 = jc * TW;
        const int g  = o * NC_ + c;
        const int ori = s_ori[g];
        const int A   = j0 + ((ori & 255) & ~1) - 8;
        const int ri0 = i0 + (ori >> 8) - 8;
        const float* __restrict__ xc =
            x + ((size_t)b * NC_ + c) * (NXL * NYL);
#pragma unroll
        for (int pass = 0; pass < 2; ++pass) {
            if (pass == 1 && ty >= 8) break;
            const int r  = ty + pass * 32;
            const int gi = ri0 + r;
            const bool rowok = (unsigned)gi < NXL;
            const float* grow = xc + (rowok ? gi : 0) * NYL;
            char* rb = tbuf + r * ROWB;
#pragma unroll
            for (int m = 0; m < 8; ++m) {
                const int gcol = A + 2 * (tx + 8 * m);
                const bool ok  = rowok && ((unsigned)gcol < NYL);
                const int dst  = swz_unit(thcu + 4 * m) * 16 + half8;
                __pipeline_memcpy_async(rb + dst,
                                        ok ? grow + gcol : (const float*)xc,
                                        8, ok ? 0 : 8);
            }
            if (tx < 6) {
                const int gcol = A + 2 * (tx + 64);
                const bool ok  = rowok && ((unsigned)gcol < NYL);
                const int dst  = swz_unit(thcu + 32) * 16 + half8;
                __pipeline_memcpy_async(rb + dst,
                                        ok ? grow + gcol : (const float*)xc,
                                        8, ok ? 0 : 8);
            }
        }
        if (tid < 81)
            __pipeline_memcpy_async(wbuf + wdoff,
                                    ((const ull*)g_w2) + (size_t)g * 81 + tid,
                                    8);
        __pipeline_commit();
    };

    // per-thread swizzled E unit byte offsets (row-independent)
    int offs[7];
#pragma unroll
    for (int e = 0; e < 7; ++e)
        offs[e] = ty * ROWB + swz_unit(4 * tx + e) * 16;

    int tile = s_t[0];
    if (tile < NTILES) {
        stage(tile, 0, bufs[0], wbs[0]);
        __pipeline_wait_prior(0);
        __syncthreads();
    }

    int par = 0;
    while (tile < NTILES) {
        ull accA[8], accB[9];
#pragma unroll
        for (int j = 0; j < 8; ++j) accA[j] = 0ull;
#pragma unroll
        for (int i = 0; i < 9; ++i) accB[i] = 0ull;

        const int jc = tile & 1, ir = (tile >> 1) & 7, r3 = tile >> 4;
        const int b = r3 / 3, o = r3 - 3 * b;
        int nt = NTILES;

        for (int c = 0; c < NC_; ++c) {
            if (c == 28 && tid == 0)
                s_t[0] = (int)atomicAdd(&g_tilectr, 1u);  // publish @ c=28 bar
            if (c + 1 < NC_) {
                stage(tile, c + 1, bufs[par ^ 1], wbs[par ^ 1]);
            } else {
                nt = s_t[0];
                if (nt < NTILES) stage(nt, 0, bufs[par ^ 1], wbs[par ^ 1]);
            }

            if (s_ori[o * NC_ + c] & 1)
                channel_math<1>(bufs[par], wbs[par], offs, accA, accB);
            else
                channel_math<0>(bufs[par], wbs[par], offs, accA, accB);

            __pipeline_wait_prior(0);
            __syncthreads();
            par ^= 1;
        }

        // epilogue: merge dual-phase accumulators, write 16 cols
        float res[16];
#pragma unroll
        for (int j = 0; j < 8; ++j) {
            float aLo = __uint_as_float((unsigned)(accA[j] & 0xffffffffull));
            float aHi = __uint_as_float((unsigned)(accA[j] >> 32));
            float bHi = __uint_as_float((unsigned)(accB[j] >> 32));
            float bLo = __uint_as_float((unsigned)(accB[j + 1] & 0xffffffffull));
            res[2 * j]     = aLo + bHi;
            res[2 * j + 1] = aHi + bLo;
        }
        float* op = out + ((size_t)(b * NO_ + o) * NXL + (ir * TH + ty)) * NYL
                        + jc * TW + tx * 16;
#pragma unroll
        for (int q = 0; q < 4; ++q)
            reinterpret_cast<float4*>(op)[q] =
                make_float4(res[4 * q], res[4 * q + 1],
                            res[4 * q + 2], res[4 * q + 3]);

        tile = nt;   // next tile's channel 0 already resident in bufs[par]
    }
}

// ---------------------------------------------------------------------------
extern "C" void kernel_launch(void* const* d_in, const int* in_sizes, int n_in,
                              void* d_out, int out_size) {
    const float* x   = (const float*)d_in[0];
    const float* vk  = (const float*)d_in[1];
    const int*   loc = (const int*)d_in[2];
    float* out = (float*)d_out;

    cudaFuncSetAttribute(conv_kernel,
                         cudaFuncAttributeMaxDynamicSharedMemorySize,
                         SMEM_BYTES);

    prep_all<<<(NG_ * 32 + 255) / 256, 256>>>(vk, loc);
    conv_kernel<<<NBLOCKS, 256, SMEM_BYTES>>>(x, out);
}

// round 9
// speedup vs baseline: 1.3005x; 1.3005x over previous
#include <cuda_runtime.h>
#include <cuda_pipeline.h>

typedef unsigned long long ull;

// Problem dims
#define NC_  31
#define NXL  256
#define NYL  256
#define NO_  3
#define KXL  17
#define KYL  17
#define NG_  (NO_ * NC_)   // 93
#define WIN_ 9

// Compact weights: per (o,c) group a 9x9 tile of broadcast (v,v) float2 pairs
__device__ float2 g_w2[NG_ * 81];
__device__ int    g_ori[NG_];   // (kx0 << 8) | ky0

// ---------------------------------------------------------------------------
// Fused prep: one warp per group (origin via shfl-min, then scatter).
// ---------------------------------------------------------------------------
__global__ void prep_all(const float* __restrict__ vk,
                         const int* __restrict__ loc) {
    int w    = (blockIdx.x * blockDim.x + threadIdx.x) >> 5;
    int lane = threadIdx.x & 31;
    if (w >= NG_) return;

    int kxm = 1 << 30, kym = 1 << 30;
    int idxs[3]; float vs[3];
#pragma unroll
    for (int s = 0; s < 3; ++s) {
        int t = lane + 32 * s;
        if (t < 81) {
            int idx = loc[w * 81 + t];
            idxs[s] = idx;
            vs[s]   = vk[w * 81 + t];
            int ky = idx % KYL;
            int kx = (idx / KYL) % KXL;
            kxm = min(kxm, kx);
            kym = min(kym, ky);
        }
    }
#pragma unroll
    for (int off = 16; off; off >>= 1) {
        kxm = min(kxm, __shfl_xor_sync(0xffffffffu, kxm, off));
        kym = min(kym, __shfl_xor_sync(0xffffffffu, kym, off));
    }
    if (lane == 0) g_ori[w] = (kxm << 8) | kym;

#pragma unroll
    for (int s = 0; s < 3; ++s) {
        int t = lane + 32 * s;
        if (t < 81) {
            int idx = idxs[s];
            float v = fmaxf(vs[s], 0.0f);
            int ky = idx % KYL;
            int kx = (idx / KYL) % KXL;
            g_w2[w * 81 + (kx - kxm) * WIN_ + (ky - kym)] = make_float2(v, v);
        }
    }
}

// ---------------------------------------------------------------------------
// Main conv (round-7 structure). Block = 256 threads, tile 32x128 per (b,o).
// 8B-aligned cp.async staging; parity absorbed by dual-phase accumulators.
// NEW: in-place register pipeline -- next-tap-row units load directly into
// the P register pairs that just died (no N[] staging array, no copies), and
// the first weight pair of the next tap-row is prefetched during the current
// one, so no load sits immediately before its first use.
// ---------------------------------------------------------------------------
#define TH 32
#define TW 128
#define SRO 40                 // staged rows (TH + 8)
#define SWF 160                // smem row stride in floats
#define ROWB (SWF * 4)         // 640 bytes
#define TILE_B (SRO * ROWB)    // 25600 bytes
#define WPAD 10                // weight row stride in ull
#define WBUF (WIN_ * WPAD)     // 90 ull
#define SMEM_BYTES (2 * TILE_B + 2 * WBUF * 8 + NC_ * 4)  // 52764

#define FMA2(acc, a, b) \
    asm("fma.rn.f32x2 %0, %1, %2, %0;" : "+l"(acc) : "l"(a), "l"(b))

__device__ __forceinline__ int swz_unit(int cu) {
    return cu ^ ((cu >> 3) & 7);
}

__device__ __forceinline__ void ldE(const char* p, ull& a, ull& b) {
    longlong2 L = *(const longlong2*)p;
    a = (ull)L.x; b = (ull)L.y;
}

__device__ __forceinline__ void fmaA(ull* acc, const ull* p, ull w) {
#pragma unroll
    for (int j = 0; j < 8; ++j) FMA2(acc[j], p[j], w);
}
__device__ __forceinline__ void fmaB(ull* acc, const ull* p, ull w) {
#pragma unroll
    for (int i = 0; i < 9; ++i) FMA2(acc[i], p[i], w);
}

// Channel math, parity SV = ky0 & 1. P[2e],P[2e+1] = pairs of unit e of the
// current tap row. accA[j]=(out2j,out2j+1); accB[i]=(out2i-1,out2i).
// Group order SV0: A0 B0 A1 B1 A2 B2 A3 B3 A4 (A_t reads P[t..t+7],
// B_t reads P[t..t+8]).  SV1: B0 A1 B1 A2 B2 A3 B3 A4 B4 (shifted).
// Death schedule drives the in-place next-row loads.
template<int SV>
__device__ __forceinline__ void channel_math(
        const char* __restrict__ tb, const char* __restrict__ wb,
        const int* offs, ull* accA, ull* accB) {
    ull P[14];
#pragma unroll
    for (int e = 0; e < (SV ? 7 : 6); ++e)
        ldE(tb + offs[e], P[2 * e], P[2 * e + 1]);
    ull wp0, wp1;
    ldE(wb, wp0, wp1);                        // taps 0,1 of u=0

#pragma unroll
    for (int u = 0; u < 9; ++u) {
        const char* wr = wb + u * 80;
        const int rn = (u + 1) * ROWB;
        ull w2, w3, w4, w5, w6, w7;
        ldE(wr + 16, w2, w3);

        if (SV == 0) { fmaA(accA, P + 0, wp0); fmaB(accB, P + 0, wp1); }
        else         { fmaB(accB, P + 0, wp0); fmaA(accA, P + 1, wp1); }

        ldE(wr + 32, w4, w5);
        ldE(wr + 48, w6, w7);
        const ull w8 = *(const ull*)(wr + 64);

        if (SV == 0) { fmaA(accA, P + 1, w2); fmaB(accB, P + 1, w3); }
        else         { fmaB(accB, P + 1, w2); fmaA(accA, P + 2, w3); }

        if (u < 8) ldE(tb + offs[0] + rn, P[0], P[1]);   // unit0 next row

        if (SV == 0) { fmaA(accA, P + 2, w4); fmaB(accB, P + 2, w5); }
        else         { fmaB(accB, P + 2, w4); fmaA(accA, P + 3, w5); }

        if (SV == 0) { fmaA(accA, P + 3, w6); fmaB(accB, P + 3, w7); }
        else         { fmaB(accB, P + 3, w6); fmaA(accA, P + 4, w7); }

        if (u < 8) {
            ldE(tb + offs[1] + rn, P[2], P[3]);          // unit1 next row
            ldE(wr + 80, wp0, wp1);                      // taps 0,1 of u+1
        }

        if (SV == 0) fmaA(accA, P + 4, w8);
        else         fmaB(accB, P + 4, w8);

        if (u < 8) {                                     // units 2..5(6) next
            ldE(tb + offs[2] + rn, P[4],  P[5]);
            ldE(tb + offs[3] + rn, P[6],  P[7]);
            ldE(tb + offs[4] + rn, P[8],  P[9]);
            ldE(tb + offs[5] + rn, P[10], P[11]);
            if (SV == 1) ldE(tb + offs[6] + rn, P[12], P[13]);
        }
    }
}

__global__ void __launch_bounds__(256, 3) conv_kernel(
        const float* __restrict__ x, float* __restrict__ out) {
    extern __shared__ float smem[];
    char* buf0 = (char*)smem;
    char* buf1 = buf0 + TILE_B;
    char* wb0  = buf1 + TILE_B;
    char* wb1  = wb0 + WBUF * 8;
    int*  s_ori = (int*)(wb1 + WBUF * 8);

    const int tid = threadIdx.x;
    const int tx  = tid & 7;          // 16-col group
    const int ty  = tid >> 3;         // output row 0..31

    const int o  = blockIdx.y;
    const int b  = blockIdx.z;
    const int i0 = (blockIdx.x >> 1) * TH;
    const int j0 = (blockIdx.x & 1) * TW;

    if (tid < NC_) s_ori[tid] = g_ori[o * NC_ + tid];
    __syncthreads();

    const float* __restrict__ xb = x + (size_t)b * NC_ * NXL * NYL;
    const int wdoff = ((tid / WIN_) * WPAD + tid % WIN_) * 8;
    const int half8 = (tx & 1) * 8;
    const int thcu  = tx >> 1;

    // ---- async staging of one channel (8B granular, aligned origin) ----
    auto stage = [&](int c, char* tbuf, char* wbuf) {
        const int ori = s_ori[c];
        const int kx0 = ori >> 8, ky0 = ori & 255;
        const int A   = j0 + (ky0 & ~1) - 8;   // even, 8B-aligned gmem origin
        const int ri0 = i0 + kx0 - 8;
        const float* __restrict__ xc = xb + (size_t)c * (NXL * NYL);
#pragma unroll
        for (int pass = 0; pass < 2; ++pass) {
            if (pass == 1 && ty >= 8) break;
            const int r  = ty + pass * 32;
            const int gi = ri0 + r;
            const bool rowok = (unsigned)gi < NXL;
            const float* grow = xc + (rowok ? gi : 0) * NYL;
            char* rb = tbuf + r * ROWB;
#pragma unroll
            for (int m = 0; m < 8; ++m) {
                const int gcol = A + 2 * (tx + 8 * m);
                const bool ok  = rowok && ((unsigned)gcol < NYL);
                const int dst  = swz_unit(thcu + 4 * m) * 16 + half8;
                __pipeline_memcpy_async(rb + dst,
                                        ok ? grow + gcol : (const float*)xc,
                                        8, ok ? 0 : 8);
            }
            if (tx < 6) {   // tail: dwords 64..69
                const int gcol = A + 2 * (tx + 64);
                const bool ok  = rowok && ((unsigned)gcol < NYL);
                const int dst  = swz_unit(thcu + 32) * 16 + half8;
                __pipeline_memcpy_async(rb + dst,
                                        ok ? grow + gcol : (const float*)xc,
                                        8, ok ? 0 : 8);
            }
        }
        if (tid < 81)
            __pipeline_memcpy_async(wbuf + wdoff,
                                    ((const ull*)g_w2)
                                        + (size_t)(o * NC_ + c) * 81 + tid,
                                    8);
        __pipeline_commit();
    };

    // per-thread swizzled E unit byte offsets (row-independent)
    int offs[7];
#pragma unroll
    for (int e = 0; e < 7; ++e)
        offs[e] = ty * ROWB + swz_unit(4 * tx + e) * 16;

    ull accA[8], accB[9];
#pragma unroll
    for (int j = 0; j < 8; ++j) accA[j] = 0ull;
#pragma unroll
    for (int i = 0; i < 9; ++i) accB[i] = 0ull;

    stage(0, buf0, wb0);
    __pipeline_wait_prior(0);
    __syncthreads();

    for (int c = 0; c < NC_; ++c) {
        if (c + 1 < NC_)
            stage(c + 1, (c & 1) ? buf0 : buf1, (c & 1) ? wb0 : wb1);

        const char* tb = (c & 1) ? buf1 : buf0;
        const char* wb = (c & 1) ? wb1 : wb0;

        if (s_ori[c] & 1) channel_math<1>(tb, wb, offs, accA, accB);
        else              channel_math<0>(tb, wb, offs, accA, accB);

        __pipeline_wait_prior(0);
        __syncthreads();
    }

    // ---- epilogue: merge dual-phase accumulators, write 16 cols ----
    float res[16];
#pragma unroll
    for (int j = 0; j < 8; ++j) {
        float aLo = __uint_as_float((unsigned)(accA[j] & 0xffffffffull));
        float aHi = __uint_as_float((unsigned)(accA[j] >> 32));
        float bHi = __uint_as_float((unsigned)(accB[j] >> 32));
        float bLo = __uint_as_float((unsigned)(accB[j + 1] & 0xffffffffull));
        res[2 * j]     = aLo + bHi;
        res[2 * j + 1] = aHi + bLo;
    }
    float* op = out + ((size_t)(b * NO_ + o) * NXL + (i0 + ty)) * NYL
                    + j0 + tx * 16;
#pragma unroll
    for (int q = 0; q < 4; ++q)
        reinterpret_cast<float4*>(op)[q] =
            make_float4(res[4 * q], res[4 * q + 1],
                        res[4 * q + 2], res[4 * q + 3]);
}

// ---------------------------------------------------------------------------
extern "C" void kernel_launch(void* const* d_in, const int* in_sizes, int n_in,
                              void* d_out, int out_size) {
    const float* x   = (const float*)d_in[0];
    const float* vk  = (const float*)d_in[1];
    const int*   loc = (const int*)d_in[2];
    float* out = (float*)d_out;

    cudaFuncSetAttribute(conv_kernel,
                         cudaFuncAttributeMaxDynamicSharedMemorySize,
                         SMEM_BYTES);

    prep_all<<<(NG_ * 32 + 255) / 256, 256>>>(vk, loc);

    dim3 grid((NXL / TH) * (NYL / TW), NO_, 16);  // (16, 3, 16)
    conv_kernel<<<grid, 256, SMEM_BYTES>>>(x, out);
}